// round 15
// baseline (speedup 1.0000x reference)
#include <cuda_runtime.h>
#include <math.h>

// ---------------- device scratch ----------------
__device__ float g_blur[4 * 224 * 224 * 256];   // blurred feats, layout [b][y][x][c]
__device__ float g_wp[81 * 256];                // weights repacked [k*9+tap][c]
__device__ int   g_mask_mode;                   // 0=uint8, 1=int32, 2=float32

// ---------------- mask dtype detection ----------------
__global__ void detect_mask_kernel(const unsigned* __restrict__ m) {
    int lane = threadIdx.x;  // 32 threads
    int fcount = 0, zocount = 0;
#pragma unroll
    for (int i = 0; i < 8; i++) {
        unsigned w = m[lane * 8 + i];
        if (w == 0x3f800000u) fcount++;
        if (w <= 1u) zocount++;
    }
#pragma unroll
    for (int o = 16; o; o >>= 1) {
        fcount  += __shfl_xor_sync(0xffffffffu, fcount, o);
        zocount += __shfl_xor_sync(0xffffffffu, zocount, o);
    }
    if (lane == 0) g_mask_mode = (fcount > 0) ? 2 : ((zocount == 256) ? 1 : 0);
}

// ---------------- weight repack: (9,256,3,3) -> [k*9+tap][c] ----------------
__global__ void repack_kernel(const float* __restrict__ ak) {
    int idx = blockIdx.x * 256 + threadIdx.x;  // 81 blocks * 256 = 20736
    int c  = idx & 255;
    int kt = idx >> 8;           // k*9 + tap, 0..80
    int k = kt / 9, tap = kt - k * 9;
    g_wp[idx] = ak[(k * 256 + c) * 9 + tap];
}

// ---------------- separable 5x5 gaussian blur (proven R3 config) -----------
#define BLUR_SMEM (32 * 593 * 4)

__global__ void __launch_bounds__(512, 2) blur_kernel(const float* __restrict__ hr) {
    extern __shared__ float s_v[];

    const float C = -1.4142135623730951f;
    float tb[5]; float s = 0.f;
#pragma unroll
    for (int j = 0; j < 5; j++) { float d = (float)(j - 2); tb[j] = expf(d * d * C); s += tb[j]; }
#pragma unroll
    for (int j = 0; j < 5; j++) tb[j] = tb[j] / s;

    int b = blockIdx.z, cb = blockIdx.y;
    int tx = blockIdx.x % 7, ty = blockIdx.x / 7;
    int x0 = tx * 32, y0 = ty * 16;
    int t = threadIdx.x;

    for (int j = t; j < 1152; j += 512) {
        int ch = j / 36, lx = j - ch * 36;
        int ix = x0 - 2 + lx;
        bool vx = (ix >= 0 && ix < 224);
        const float* base = hr + ((long)(b * 256 + cb * 32 + ch) * 224) * 224 + ix;
        float w0 = 0.f, w1 = 0.f, w2 = 0.f, w3 = 0.f, w4 = 0.f;
        float* ov = s_v + ch * 593 + lx;
#pragma unroll
        for (int yy = 0; yy < 20; yy++) {
            int iy = y0 - 2 + yy;
            float v = (vx && iy >= 0 && iy < 224) ? base[iy * 224] : 0.f;
            w0 = w1; w1 = w2; w2 = w3; w3 = w4; w4 = v;
            if (yy >= 4) {
                float o = w0*tb[0] + w1*tb[1] + w2*tb[2] + w3*tb[3] + w4*tb[4];
                ov[(yy - 4) * 37] = o;
            }
        }
    }
    __syncthreads();

    {
        int ch = t & 31, yr = t >> 5;
        const float* vp = s_v + ch * 593 + yr * 37;
        float* ob = g_blur + ((long)(b * 224 + y0 + yr) * 224 + x0) * 256 + cb * 32 + ch;
        float a0 = vp[0], a1 = vp[1], a2 = vp[2], a3 = vp[3];
#pragma unroll
        for (int x = 0; x < 32; x++) {
            float a4 = vp[x + 4];
            float o = a0*tb[0] + a1*tb[1] + a2*tb[2] + a3*tb[3] + a4*tb[4];
            ob[x * 256] = o;
            a0 = a1; a1 = a2; a2 = a3; a3 = a4;
        }
    }
}

// ---------------- fused v11: persistent, 1024 threads, cp.async pipeline ---
// Grid = 148 CTAs, 1024 threads (32 warps), 1 CTA/SM. Tile n+1's region
// prefetched (cp.async.cg) while tile n computes. Per-thread work is half
// of v10: phase B = 2 px/thread (acc[9][2]), einsum = 1 row/thread.
// smem floats: s_blur 2x22100 | s_w 4608 | s_red 576 | s_logit 144 | s_attn 144
#define GRID_F 148
#define TILES_TOTAL 3136
#define FUSED_SMEM ((44200 + 4608 + 576 + 144 + 144) * 4)

__device__ __forceinline__ void stage_tap(const float4* __restrict__ wp4,
                                          float* __restrict__ s_w,
                                          int buf, int tap, int t)
{
    // 576 float4 per tap (9 k x 64 c4); threads 0..575 carry one each
    if (t < 576) {
        int k = t >> 6, c4 = t & 63;
        *(float4*)(s_w + ((buf * 9 + k) * 64 + c4) * 4) =
            __ldg(&wp4[(k * 9 + tap) * 64 + c4]);
    }
}

// issue cp.async for tile's 85-row region into s_dst (zero-fill OOB)
__device__ __forceinline__ void prefetch_region(int tile, float* s_dst, int t) {
    int b = tile / 784;
    int rem = tile - b * 784;
    int ty = rem / 14, tx = rem - ty * 14;
    int rx0 = 2 * (tx * 8) - 1, ry0 = 2 * (ty * 2) - 1;
    int c4 = t & 63, rr = t >> 6;   // rr 0..15
    const float* gb = g_blur + (long)b * 224 * 224 * 256 + c4 * 4;
#pragma unroll
    for (int row = rr; row < 85; row += 16) {
        int riy, rix;
        if (row < 45) { riy = row / 9;  rix = 2 * (row - riy * 9); }
        else { int q = row - 45; riy = q >> 3; rix = 2 * (q & 7) + 1; }
        int iy = ry0 + riy, ix = rx0 + rix;
        bool ok = (iy >= 0 && iy < 224 && ix >= 0 && ix < 224);
        const float* src = ok ? (gb + ((long)iy * 224 + ix) * 256) : gb;
        unsigned dst = (unsigned)__cvta_generic_to_shared(s_dst + row * 260 + c4 * 4);
        int sz = ok ? 16 : 0;
        asm volatile("cp.async.cg.shared.global [%0], [%1], 16, %2;\n"
                     :: "r"(dst), "l"(src), "r"(sz));
    }
}

__global__ void __launch_bounds__(1024) fused_kernel(
    const void* __restrict__ maskp,
    const float* __restrict__ kbias,
    const float* __restrict__ lbias,
    float* __restrict__ out)
{
    extern __shared__ float sm[];
    float* s_blurA = sm;             // 2 x 22100
    float* s_w     = sm + 44200;     // 4608
    float* s_red   = sm + 48808;     // 576 = 32 warps x 18
    float* s_logit = sm + 49384;     // 144
    float* s_attn  = sm + 49528;     // 144

    int t = threadIdx.x;
    const float4* wp4 = (const float4*)g_wp;
    int mm = g_mask_mode;

    float kb_r = 0.f, lb_r = 0.f;
    if (t < 144) { int k = t % 9; kb_r = kbias[k]; lb_r = lbias[k]; }

    int n = blockIdx.x;
    int buf = 0;

    prefetch_region(n, s_blurA, t);
    asm volatile("cp.async.commit_group;\n");

    while (n < TILES_TOTAL) {
        int n2 = n + GRID_F;
        if (n2 < TILES_TOTAL)
            prefetch_region(n2, s_blurA + (buf ^ 1) * 22100, t);
        asm volatile("cp.async.commit_group;\n");   // (possibly empty group)

        stage_tap(wp4, s_w, 0, 0, t);
        asm volatile("cp.async.wait_group 1;\n");   // tile n's region resident
        __syncthreads();

        float* s_blur = s_blurA + buf * 22100;
        int b = n / 784;
        int rem = n - b * 784;
        int tyi = rem / 14, txi = rem - tyi * 14;
        int x0o = txi * 8, y0o = tyi * 2;

        // ---- phase B: thread = (c2 = t&127, pq = t>>7), 2 px x 9 k ----
        {
            int c2 = t & 127, pq = t >> 7;      // pq 0..7
            int py = pq >> 2, xq = pq & 3;      // px_i = 2*xq + i
            const float2* sb2 = (const float2*)s_blur;   // row stride 130
            const float2* sw2 = (const float2*)s_w;      // [buf*9+k]*128 + c2

            float acc[9][2];
#pragma unroll
            for (int k = 0; k < 9; k++) { acc[k][0] = 0.f; acc[k][1] = 0.f; }

#pragma unroll
            for (int tap = 0; tap < 9; tap++) {
                if (tap < 8) stage_tap(wp4, s_w, (tap + 1) & 1, tap + 1, t);

                const int dy = tap / 3, dx = tap % 3;
                int riy = 2 * py + dy;
                // rix = 4*xq + 2*i + dx -> rows r0 (i=0), r1 = r0+1 (i=1)
                int rbase = (dx & 1) ? (45 + riy * 8 + 2 * xq)
                                     : (riy * 9 + 2 * xq + (dx >> 1));
                float2 v0 = sb2[(rbase + 0) * 130 + c2];
                float2 v1 = sb2[(rbase + 1) * 130 + c2];
                int bufb = (tap & 1) * 9;
#pragma unroll
                for (int k = 0; k < 9; k++) {
                    float2 w = sw2[(bufb + k) * 128 + c2];
                    acc[k][0] = fmaf(v0.y, w.y, fmaf(v0.x, w.x, acc[k][0]));
                    acc[k][1] = fmaf(v1.y, w.y, fmaf(v1.x, w.x, acc[k][1]));
                }
                __syncthreads();
            }

            // butterfly over 32 lanes (64 channels per warp)
#pragma unroll
            for (int o = 16; o; o >>= 1)
#pragma unroll
                for (int k = 0; k < 9; k++) {
                    acc[k][0] += __shfl_xor_sync(0xffffffffu, acc[k][0], o);
                    acc[k][1] += __shfl_xor_sync(0xffffffffu, acc[k][1], o);
                }
            int w = t >> 5, lane = t & 31;
            if (lane == 0) {
#pragma unroll
                for (int k = 0; k < 9; k++) {
                    s_red[w * 18 + k * 2 + 0] = acc[k][0];
                    s_red[w * 18 + k * 2 + 1] = acc[k][1];
                }
            }
        }
        __syncthreads();

        // ---- combine 4 warp-partials + kbias + mask + lbias ----
        if (t < 144) {
            int p = t / 9, k = t - p * 9;
            int py = p >> 3, px = p & 7;
            int xq = px >> 1, i = px & 1;
            int pq = py * 4 + xq;
            float v = kb_r;
#pragma unroll
            for (int j = 0; j < 4; j++)
                v += s_red[(pq * 4 + j) * 18 + k * 2 + i];
            int oy = y0o + py, ox = x0o + px;
            long midx = ((long)(b * 9 + k) * 112 + oy) * 112 + ox;
            bool keep;
            if (mm == 0)      keep = ((const unsigned char*)maskp)[midx] != 0;
            else if (mm == 1) keep = ((const int*)maskp)[midx] != 0;
            else              keep = ((const float*)maskp)[midx] != 0.f;
            s_logit[p * 9 + k] = (keep ? v : 0.f) + lb_r;
        }
        __syncthreads();

        // ---- softmax over 9 ----
        if (t < 16) {
            int p = t;
            float lg[9];
#pragma unroll
            for (int k = 0; k < 9; k++) lg[k] = s_logit[p * 9 + k];
            float mx = lg[0];
#pragma unroll
            for (int k = 1; k < 9; k++) mx = fmaxf(mx, lg[k]);
            float e[9]; float ssum = 0.f;
#pragma unroll
            for (int k = 0; k < 9; k++) { e[k] = expf(lg[k] - mx); ssum += e[k]; }
            float invs = 1.0f / ssum;
#pragma unroll
            for (int k = 0; k < 9; k++) s_attn[p * 9 + k] = e[k] * invs;
        }
        __syncthreads();

        // ---- einsum: thread = (px = t&7, c4 = (t>>3)&63, r = t>>9) ----
        {
            int px = t & 7, c4 = (t >> 3) & 63, r = t >> 9;
            const float4* sb4 = (const float4*)s_blur;
            float4 o = make_float4(0.f, 0.f, 0.f, 0.f);
#pragma unroll
            for (int dy = 0; dy < 3; dy++) {
                int riy = 2 * r + dy;
#pragma unroll
                for (int dx = 0; dx < 3; dx++) {
                    int rix = 2 * px + dx;
                    int row = (rix & 1) ? (45 + riy * 8 + (rix >> 1))
                                        : (riy * 9 + (rix >> 1));
                    float4 v = sb4[row * 65 + c4];
                    float a = s_attn[(r * 8 + px) * 9 + dy * 3 + dx];
                    o.x = fmaf(v.x, a, o.x);
                    o.y = fmaf(v.y, a, o.y);
                    o.z = fmaf(v.z, a, o.z);
                    o.w = fmaf(v.w, a, o.w);
                }
            }
            long base = ((long)(b * 256 + c4 * 4) * 112 + y0o + r) * 112 + x0o + px;
            const long cs = (long)112 * 112;
            out[base]          = o.x;
            out[base + cs]     = o.y;
            out[base + 2 * cs] = o.z;
            out[base + 3 * cs] = o.w;
        }
        __syncthreads();   // protect region buffer & s_attn before next tile

        buf ^= 1;
        n = n2;
    }
}

// ---------------- launch ----------------
extern "C" void kernel_launch(void* const* d_in, const int* in_sizes, int n_in,
                              void* d_out, int out_size) {
    const float* hr  = (const float*)d_in[0];
    const float* ak  = (const float*)d_in[1];
    const float* kb  = (const float*)d_in[2];
    const float* lb  = (const float*)d_in[3];
    const void*  msk = d_in[4];
    float* out = (float*)d_out;
    (void)in_sizes; (void)n_in; (void)out_size;

    cudaFuncSetAttribute(blur_kernel,  cudaFuncAttributeMaxDynamicSharedMemorySize, BLUR_SMEM);
    cudaFuncSetAttribute(fused_kernel, cudaFuncAttributeMaxDynamicSharedMemorySize, FUSED_SMEM);

    detect_mask_kernel<<<1, 32>>>((const unsigned*)msk);
    repack_kernel<<<81, 256>>>(ak);
    blur_kernel<<<dim3(98, 8, 4), 512, BLUR_SMEM>>>(hr);
    fused_kernel<<<GRID_F, 1024, FUSED_SMEM>>>(msk, kb, lb, out);
}

// round 16
// speedup vs baseline: 1.1208x; 1.1208x over previous
#include <cuda_runtime.h>
#include <math.h>

// ---------------- device scratch ----------------
__device__ float g_blur[4 * 224 * 224 * 256];   // blurred feats, layout [b][y][x][c]
__device__ float g_wp[81 * 256];                // weights repacked [k*9+tap][c]
__device__ int   g_mask_mode;                   // 0=uint8, 1=int32, 2=float32

// ---------------- mask dtype detection ----------------
__global__ void detect_mask_kernel(const unsigned* __restrict__ m) {
    int lane = threadIdx.x;  // 32 threads
    int fcount = 0, zocount = 0;
#pragma unroll
    for (int i = 0; i < 8; i++) {
        unsigned w = m[lane * 8 + i];
        if (w == 0x3f800000u) fcount++;
        if (w <= 1u) zocount++;
    }
#pragma unroll
    for (int o = 16; o; o >>= 1) {
        fcount  += __shfl_xor_sync(0xffffffffu, fcount, o);
        zocount += __shfl_xor_sync(0xffffffffu, zocount, o);
    }
    if (lane == 0) g_mask_mode = (fcount > 0) ? 2 : ((zocount == 256) ? 1 : 0);
}

// ---------------- weight repack: (9,256,3,3) -> [k*9+tap][c] ----------------
__global__ void repack_kernel(const float* __restrict__ ak) {
    int idx = blockIdx.x * 256 + threadIdx.x;  // 81 blocks * 256 = 20736
    int c  = idx & 255;
    int kt = idx >> 8;           // k*9 + tap, 0..80
    int k = kt / 9, tap = kt - k * 9;
    g_wp[idx] = ak[(k * 256 + c) * 9 + tap];
}

// ---------------- separable 5x5 gaussian blur (proven R3 config) -----------
#define BLUR_SMEM (32 * 593 * 4)

__global__ void __launch_bounds__(512, 2) blur_kernel(const float* __restrict__ hr) {
    extern __shared__ float s_v[];

    const float C = -1.4142135623730951f;
    float tb[5]; float s = 0.f;
#pragma unroll
    for (int j = 0; j < 5; j++) { float d = (float)(j - 2); tb[j] = expf(d * d * C); s += tb[j]; }
#pragma unroll
    for (int j = 0; j < 5; j++) tb[j] = tb[j] / s;

    int b = blockIdx.z, cb = blockIdx.y;
    int tx = blockIdx.x % 7, ty = blockIdx.x / 7;
    int x0 = tx * 32, y0 = ty * 16;
    int t = threadIdx.x;

    for (int j = t; j < 1152; j += 512) {
        int ch = j / 36, lx = j - ch * 36;
        int ix = x0 - 2 + lx;
        bool vx = (ix >= 0 && ix < 224);
        const float* base = hr + ((long)(b * 256 + cb * 32 + ch) * 224) * 224 + ix;
        float w0 = 0.f, w1 = 0.f, w2 = 0.f, w3 = 0.f, w4 = 0.f;
        float* ov = s_v + ch * 593 + lx;
#pragma unroll
        for (int yy = 0; yy < 20; yy++) {
            int iy = y0 - 2 + yy;
            float v = (vx && iy >= 0 && iy < 224) ? base[iy * 224] : 0.f;
            w0 = w1; w1 = w2; w2 = w3; w3 = w4; w4 = v;
            if (yy >= 4) {
                float o = w0*tb[0] + w1*tb[1] + w2*tb[2] + w3*tb[3] + w4*tb[4];
                ov[(yy - 4) * 37] = o;
            }
        }
    }
    __syncthreads();

    {
        int ch = t & 31, yr = t >> 5;
        const float* vp = s_v + ch * 593 + yr * 37;
        float* ob = g_blur + ((long)(b * 224 + y0 + yr) * 224 + x0) * 256 + cb * 32 + ch;
        float a0 = vp[0], a1 = vp[1], a2 = vp[2], a3 = vp[3];
#pragma unroll
        for (int x = 0; x < 32; x++) {
            float a4 = vp[x + 4];
            float o = a0*tb[0] + a1*tb[1] + a2*tb[2] + a3*tb[3] + a4*tb[4];
            ob[x * 256] = o;
            a0 = a1; a1 = a2; a2 = a3; a3 = a4;
        }
    }
}

// ---------------- fused v12: v10 + cheap reduction + v-reuse ---------------
// Persistent: grid 148, 512 threads, 1 CTA/SM. Region n+1 prefetched via
// cp.async while tile n computes; weights staged per tap (double buffer).
// Phase B thread = (c2 = t&127, pg = t>>7): 4 px (px = 4*xh + i), 9 k.
//   Per dy: load 9 unique row-float2s once (ve[5], vo[4]); 3 dx-taps reuse.
// Reduction: 2-level butterfly (16,8) -> lanes 0..7 hold 4-lane sums ->
//   9 STS.128/warp into s_red[pg][k][cblk*8+lane][i]; combine = 32 partials.
// smem floats: s_blur 2x22100 | s_w 4608 | s_red 4608 | s_logit 144 | s_attn 144
#define GRID_F 148
#define TILES_TOTAL 3136
#define FUSED_SMEM ((44200 + 4608 + 4608 + 144 + 144) * 4)

__device__ __forceinline__ void stage_tap(const float4* __restrict__ wp4,
                                          float* __restrict__ s_w,
                                          int buf, int tap, int t)
{
    {
        int k = t >> 6, c4 = t & 63;
        *(float4*)(s_w + ((buf * 9 + k) * 64 + c4) * 4) =
            __ldg(&wp4[(k * 9 + tap) * 64 + c4]);
    }
    if (t < 64) {
        *(float4*)(s_w + ((buf * 9 + 8) * 64 + t) * 4) =
            __ldg(&wp4[(8 * 9 + tap) * 64 + t]);
    }
}

// issue cp.async for tile's 85-row region into s_dst (zero-fill OOB)
__device__ __forceinline__ void prefetch_region(int tile, float* s_dst, int t) {
    int b = tile / 784;
    int rem = tile - b * 784;
    int ty = rem / 14, tx = rem - ty * 14;
    int rx0 = 2 * (tx * 8) - 1, ry0 = 2 * (ty * 2) - 1;
    int c4 = t & 63, rr = t >> 6;
    const float* gb = g_blur + (long)b * 224 * 224 * 256 + c4 * 4;
#pragma unroll
    for (int row = rr; row < 85; row += 8) {
        int riy, rix;
        if (row < 45) { riy = row / 9;  rix = 2 * (row - riy * 9); }
        else { int q = row - 45; riy = q >> 3; rix = 2 * (q & 7) + 1; }
        int iy = ry0 + riy, ix = rx0 + rix;
        bool ok = (iy >= 0 && iy < 224 && ix >= 0 && ix < 224);
        const float* src = ok ? (gb + ((long)iy * 224 + ix) * 256) : gb;
        unsigned dst = (unsigned)__cvta_generic_to_shared(s_dst + row * 260 + c4 * 4);
        int sz = ok ? 16 : 0;
        asm volatile("cp.async.cg.shared.global [%0], [%1], 16, %2;\n"
                     :: "r"(dst), "l"(src), "r"(sz));
    }
}

__global__ void __launch_bounds__(512) fused_kernel(
    const void* __restrict__ maskp,
    const float* __restrict__ kbias,
    const float* __restrict__ lbias,
    float* __restrict__ out)
{
    extern __shared__ float sm[];
    float* s_blurA = sm;             // 2 x 22100
    float* s_w     = sm + 44200;     // 4608
    float* s_red   = sm + 48808;     // 4608 = 4 pg x 9 k x 32 partials x 4 i
    float* s_logit = sm + 53416;     // 144
    float* s_attn  = sm + 53560;     // 144

    int t = threadIdx.x;
    const float4* wp4 = (const float4*)g_wp;
    int mm = g_mask_mode;

    float kb_r = 0.f, lb_r = 0.f;
    if (t < 144) { int k = t % 9; kb_r = kbias[k]; lb_r = lbias[k]; }

    int n = blockIdx.x;
    int buf = 0;

    prefetch_region(n, s_blurA, t);
    asm volatile("cp.async.commit_group;\n");

    while (n < TILES_TOTAL) {
        int n2 = n + GRID_F;
        if (n2 < TILES_TOTAL)
            prefetch_region(n2, s_blurA + (buf ^ 1) * 22100, t);
        asm volatile("cp.async.commit_group;\n");

        stage_tap(wp4, s_w, 0, 0, t);
        asm volatile("cp.async.wait_group 1;\n");   // tile n's region resident
        __syncthreads();

        float* s_blur = s_blurA + buf * 22100;
        int b = n / 784;
        int rem = n - b * 784;
        int tyi = rem / 14, txi = rem - tyi * 14;
        int x0o = txi * 8, y0o = tyi * 2;

        // ---- phase B: thread = (c2, pg), 4 px x 9 k; v reused per dy ----
        {
            int c2 = t & 127, pg = t >> 7;      // pg 0..3
            int py = pg >> 1, xh = pg & 1;      // px_i = 4*xh + i
            const float2* sb2 = (const float2*)s_blur;   // row stride 130
            const float2* sw2 = (const float2*)s_w;      // [buf*9+k]*128 + c2

            float acc[9][4];
#pragma unroll
            for (int k = 0; k < 9; k++)
#pragma unroll
                for (int i = 0; i < 4; i++) acc[k][i] = 0.f;

#pragma unroll
            for (int dy = 0; dy < 3; dy++) {
                int riy = 2 * py + dy;
                int eb = riy * 9 + 4 * xh;        // even-rix rows (dx=0: +0..3, dx=2: +1..4)
                int ob = 45 + riy * 8 + 4 * xh;   // odd-rix rows (dx=1: +0..3)
                float2 ve[5], vo[4];
#pragma unroll
                for (int j = 0; j < 5; j++) ve[j] = sb2[(eb + j) * 130 + c2];
#pragma unroll
                for (int j = 0; j < 4; j++) vo[j] = sb2[(ob + j) * 130 + c2];

#pragma unroll
                for (int dx = 0; dx < 3; dx++) {
                    int tap = dy * 3 + dx;
                    if (tap < 8) stage_tap(wp4, s_w, (tap + 1) & 1, tap + 1, t);
                    int bufb = (tap & 1) * 9;
#pragma unroll
                    for (int k = 0; k < 9; k++) {
                        float2 w = sw2[(bufb + k) * 128 + c2];
#pragma unroll
                        for (int i = 0; i < 4; i++) {
                            float2 v = (dx == 1) ? vo[i] : ve[i + (dx >> 1)];
                            acc[k][i] = fmaf(v.y, w.y, fmaf(v.x, w.x, acc[k][i]));
                        }
                    }
                    __syncthreads();   // staged tap+1 visible; buffer rotation safe
                }
            }

            // 2-level butterfly: lanes 0..7 hold sums of {l, l+8, l+16, l+24}
#pragma unroll
            for (int o = 16; o >= 8; o >>= 1)
#pragma unroll
                for (int k = 0; k < 9; k++)
#pragma unroll
                    for (int i = 0; i < 4; i++)
                        acc[k][i] += __shfl_xor_sync(0xffffffffu, acc[k][i], o);

            int w = t >> 5, lane = t & 31;
            int pgw = w >> 2, cblk = w & 3;
            if (lane < 8) {
#pragma unroll
                for (int k = 0; k < 9; k++)
                    *(float4*)(s_red + ((pgw * 9 + k) * 32 + cblk * 8 + lane) * 4) =
                        make_float4(acc[k][0], acc[k][1], acc[k][2], acc[k][3]);
            }
        }
        __syncthreads();

        // ---- combine 32 partials + kbias + mask + lbias ----
        if (t < 144) {
            int p = t / 9, k = t - p * 9;
            int py = p >> 3, px = p & 7;
            int xh = px >> 2, i = px & 3;
            int pg = py * 2 + xh;
            const float* rp = s_red + (pg * 9 + k) * 128 + i;
            float s0 = 0.f, s1 = 0.f, s2 = 0.f, s3 = 0.f;
#pragma unroll
            for (int j = 0; j < 32; j += 4) {
                s0 += rp[(j + 0) * 4];
                s1 += rp[(j + 1) * 4];
                s2 += rp[(j + 2) * 4];
                s3 += rp[(j + 3) * 4];
            }
            float v = kb_r + ((s0 + s1) + (s2 + s3));
            int oy = y0o + py, ox = x0o + px;
            long midx = ((long)(b * 9 + k) * 112 + oy) * 112 + ox;
            bool keep;
            if (mm == 0)      keep = ((const unsigned char*)maskp)[midx] != 0;
            else if (mm == 1) keep = ((const int*)maskp)[midx] != 0;
            else              keep = ((const float*)maskp)[midx] != 0.f;
            s_logit[p * 9 + k] = (keep ? v : 0.f) + lb_r;
        }
        __syncthreads();

        // ---- softmax over 9 ----
        if (t < 16) {
            int p = t;
            float lg[9];
#pragma unroll
            for (int k = 0; k < 9; k++) lg[k] = s_logit[p * 9 + k];
            float mx = lg[0];
#pragma unroll
            for (int k = 1; k < 9; k++) mx = fmaxf(mx, lg[k]);
            float e[9]; float ssum = 0.f;
#pragma unroll
            for (int k = 0; k < 9; k++) { e[k] = expf(lg[k] - mx); ssum += e[k]; }
            float invs = 1.0f / ssum;
#pragma unroll
            for (int k = 0; k < 9; k++) s_attn[p * 9 + k] = e[k] * invs;
        }
        __syncthreads();

        // ---- einsum: thread = (px = t&7, c4 = t>>3), float4 channels ----
        {
            int px = t & 7, c4 = t >> 3;
            const float4* sb4 = (const float4*)s_blur;
#pragma unroll
            for (int r = 0; r < 2; r++) {
                float4 o = make_float4(0.f, 0.f, 0.f, 0.f);
#pragma unroll
                for (int dy = 0; dy < 3; dy++) {
                    int riy = 2 * r + dy;
#pragma unroll
                    for (int dx = 0; dx < 3; dx++) {
                        int rix = 2 * px + dx;
                        int row = (rix & 1) ? (45 + riy * 8 + (rix >> 1))
                                            : (riy * 9 + (rix >> 1));
                        float4 v = sb4[row * 65 + c4];
                        float a = s_attn[(r * 8 + px) * 9 + dy * 3 + dx];
                        o.x = fmaf(v.x, a, o.x);
                        o.y = fmaf(v.y, a, o.y);
                        o.z = fmaf(v.z, a, o.z);
                        o.w = fmaf(v.w, a, o.w);
                    }
                }
                long base = ((long)(b * 256 + c4 * 4) * 112 + y0o + r) * 112 + x0o + px;
                const long cs = (long)112 * 112;
                out[base]          = o.x;
                out[base + cs]     = o.y;
                out[base + 2 * cs] = o.z;
                out[base + 3 * cs] = o.w;
            }
        }
        __syncthreads();   // protect region buffer & s_attn before next tile

        buf ^= 1;
        n = n2;
    }
}

// ---------------- launch ----------------
extern "C" void kernel_launch(void* const* d_in, const int* in_sizes, int n_in,
                              void* d_out, int out_size) {
    const float* hr  = (const float*)d_in[0];
    const float* ak  = (const float*)d_in[1];
    const float* kb  = (const float*)d_in[2];
    const float* lb  = (const float*)d_in[3];
    const void*  msk = d_in[4];
    float* out = (float*)d_out;
    (void)in_sizes; (void)n_in; (void)out_size;

    cudaFuncSetAttribute(blur_kernel,  cudaFuncAttributeMaxDynamicSharedMemorySize, BLUR_SMEM);
    cudaFuncSetAttribute(fused_kernel, cudaFuncAttributeMaxDynamicSharedMemorySize, FUSED_SMEM);

    detect_mask_kernel<<<1, 32>>>((const unsigned*)msk);
    repack_kernel<<<81, 256>>>(ak);
    blur_kernel<<<dim3(98, 8, 4), 512, BLUR_SMEM>>>(hr);
    fused_kernel<<<GRID_F, 512, FUSED_SMEM>>>(msk, kb, lb, out);
}